// round 4
// baseline (speedup 1.0000x reference)
#include <cuda_runtime.h>
#include <cuda_fp16.h>
#include <cstdint>

// ============================================================================
// CKAN layer == single GEMM: out[c,p] = W[128,6912] @ F[6912,8192]
//   k = s*12 + j ; j=0 -> silu(u[s,p]) weighted by base_w
//                  j=1..11 -> cubic B-spline basis_j(u) weighted by sw*coeff
// F is built on the fly in SMEM (reuse factor of F is 1 -> never materialize).
// W precomputed to a __device__ global (1.77 MB, L2-broadcast to all CTAs).
// GEMM: ldmatrix + mma.sync.m16n8k16 (plain-sm_103-compatible; tcgen05 is
// rejected by this harness's non-'a' PTX target).
// ============================================================================
static constexpr int SIZE_S  = 576;            // 64 in-ch * 9 taps
static constexpr int NFEAT   = 12;             // silu + 11 basis
static constexpr int K_TOTAL = SIZE_S * NFEAT; // 6912
static constexpr int OUT_CH  = 128;
static constexpr int KC      = 48;             // K per chunk = 4 s-entries * 12
static constexpr int NIT     = K_TOTAL / KC;   // 144
static constexpr int SA      = 56;             // A smem row stride (halves), 112B
static constexpr int SB      = 72;             // B smem row stride (halves), 144B

__device__ __half g_W[(size_t)OUT_CH * K_TOTAL];   // packed weights, fp16

// ---------------------------------------------------------------------------
// PTX wrappers (all baseline sm_80-era instructions)
// ---------------------------------------------------------------------------
__device__ __forceinline__ uint32_t smem_u32(const void* p) {
    uint32_t a;
    asm("{ .reg .u64 t; cvta.to.shared.u64 t, %1; cvt.u32.u64 %0, t; }"
        : "=r"(a) : "l"(p));
    return a;
}

__device__ __forceinline__ void ldsm_x4(uint32_t* r, uint32_t addr) {
    asm volatile("ldmatrix.sync.aligned.m8n8.x4.shared.b16 {%0,%1,%2,%3}, [%4];"
        : "=r"(r[0]), "=r"(r[1]), "=r"(r[2]), "=r"(r[3]) : "r"(addr));
}

__device__ __forceinline__ void ldsm_x2_t(uint32_t* r, uint32_t addr) {
    asm volatile("ldmatrix.sync.aligned.m8n8.x2.trans.shared.b16 {%0,%1}, [%2];"
        : "=r"(r[0]), "=r"(r[1]) : "r"(addr));
}

__device__ __forceinline__ void mma16816(float* d, const uint32_t* a,
                                         const uint32_t* b) {
    asm volatile(
        "mma.sync.aligned.m16n8k16.row.col.f32.f16.f16.f32 "
        "{%0,%1,%2,%3}, {%4,%5,%6,%7}, {%8,%9}, {%0,%1,%2,%3};"
        : "+f"(d[0]), "+f"(d[1]), "+f"(d[2]), "+f"(d[3])
        : "r"(a[0]), "r"(a[1]), "r"(a[2]), "r"(a[3]), "r"(b[0]), "r"(b[1]));
}

// ============================================================================
// Kernel 1: pack W[c,k] fp16.  j==0 -> base_w[c,s]; j>0 -> sw[c,s]*coeff[c,s,j-1]
// ============================================================================
__global__ void build_w_kernel(const float* __restrict__ coeff,
                               const float* __restrict__ bw,
                               const float* __restrict__ sw) {
    int idx = blockIdx.x * blockDim.x + threadIdx.x;
    if (idx >= OUT_CH * K_TOTAL) return;
    int c = idx / K_TOTAL;
    int r = idx - c * K_TOTAL;
    int s = r / NFEAT;
    int j = r - s * NFEAT;
    int cs = c * SIZE_S + s;
    float v = (j == 0) ? bw[cs] : sw[cs] * coeff[cs * 11 + (j - 1)];
    g_W[idx] = __float2half(v);
}

// ============================================================================
// Kernel 2: fused F-build + GEMM.
// CTA: 64 pixels (N tile), all 128 channels (M). 256 threads = 8 warps,
// each warp a 64x16 output tile (4 m-frags x 2 n-frags of m16n8).
// ============================================================================
struct Prefetch {
    uint4 wv[3];   // this thread's slice of the next W chunk
    float v;       // this thread's unfolded input value u[s,p]
};

__device__ __forceinline__ Prefetch load_chunk(const float* __restrict__ x,
                                               int it, int tid, int poff,
                                               int n_img) {
    Prefetch pr;
    // W chunk: 128 rows x 48 halves = 768 uint4; 3 per thread, coalesced.
    #pragma unroll
    for (int r = 0; r < 3; r++) {
        int i = r * 256 + tid;
        int row = i / 6, seg = i - row * 6;
        pr.wv[r] = *reinterpret_cast<const uint4*>(
            g_W + (size_t)row * K_TOTAL + it * KC + seg * 8);
    }
    // u value: thread -> (s_local = tid>>6, p = tid&63)
    int s_local = tid >> 6, p = tid & 63;
    int s = it * 4 + s_local;
    int cin = s / 9, kk = s - cin * 9;
    int pi = poff + p;
    int iy = (pi >> 5) + kk / 3 - 1;
    int ix = (pi & 31) + (kk % 3) - 1;
    pr.v = 0.0f;
    if (iy >= 0 && iy < 32 && ix >= 0 && ix < 32)
        pr.v = __ldg(x + (((size_t)n_img * 64 + cin) << 10) + (iy << 5) + ix);
    return pr;
}

__device__ __forceinline__ void store_chunk(const Prefetch& pr, int tid,
                                            __half* sAb, __half* sBb) {
    // A tile
    #pragma unroll
    for (int r = 0; r < 3; r++) {
        int i = r * 256 + tid;
        int row = i / 6, seg = i - row * 6;
        *reinterpret_cast<uint4*>(sAb + row * SA + seg * 8) = pr.wv[r];
    }
    // F features: silu + 4-nonzero uniform cubic B-spline on grid
    // [-1.75 : 0.25 : 1.75] (degree-3 extended reference knots).
    float v = pr.v;
    float feat[NFEAT];
    feat[0] = v / (1.0f + __expf(-v));
    #pragma unroll
    for (int j = 1; j < NFEAT; j++) feat[j] = 0.0f;
    float tp = (v + 1.75f) * 4.0f;
    if (tp >= 0.0f && tp < 14.0f) {
        int m = (int)tp;
        float t = tp - (float)m, omt = 1.0f - t;
        float t2 = t * t, t3 = t2 * t;
        float b0 = omt * omt * omt * (1.0f / 6.0f);
        float b1 = (3.0f * t3 - 6.0f * t2 + 4.0f) * (1.0f / 6.0f);
        float b2 = (-3.0f * t3 + 3.0f * t2 + 3.0f * t + 1.0f) * (1.0f / 6.0f);
        float b3 = t3 * (1.0f / 6.0f);
        int j0 = m - 3;
        if (j0 >= 0     && j0 <= 10)     feat[1 + j0] = b0;
        if (j0 + 1 >= 0 && j0 + 1 <= 10) feat[2 + j0] = b1;
        if (j0 + 2 >= 0 && j0 + 2 <= 10) feat[3 + j0] = b2;
        if (j0 + 3 >= 0 && j0 + 3 <= 10) feat[4 + j0] = b3;
    }
    int s_local = tid >> 6, p = tid & 63;
    __half* col = sBb + (s_local * NFEAT) * SB + p;
    #pragma unroll
    for (int j = 0; j < NFEAT; j++) col[j * SB] = __float2half(feat[j]);
}

__global__ __launch_bounds__(256)
void fused_gemm_kernel(const float* __restrict__ x, float* __restrict__ out) {
    __shared__ __align__(16) __half sA[2][128 * SA];  // 2 x 14336 B
    __shared__ __align__(16) __half sB[2][KC * SB];   // 2 x  6912 B

    int tid  = threadIdx.x;
    int lane = tid & 31;
    int wid  = tid >> 5;
    int wm   = wid & 1;        // m-half: 0 or 1 (64 rows each)
    int wn   = wid >> 1;       // n-quarter: 0..3 (16 cols each)

    int P0    = blockIdx.x * 64;
    int n_img = P0 >> 10;
    int poff  = P0 & 1023;

    float acc[4][2][4];
    #pragma unroll
    for (int mi = 0; mi < 4; mi++)
        #pragma unroll
        for (int ni = 0; ni < 2; ni++)
            #pragma unroll
            for (int q = 0; q < 4; q++) acc[mi][ni][q] = 0.0f;

    // Precompute ldmatrix lane addressing components
    int a_row_l = (lane & 7) + (lane & 8);   // row offset within m16 tile
    int a_col_l = (lane >> 4) << 3;          // 0 or 8 within k16
    int b_row_l = lane & 15;                 // k row within k16

    // Prologue: fill buffer 0
    {
        Prefetch pr = load_chunk(x, 0, tid, poff, n_img);
        store_chunk(pr, tid, sA[0], sB[0]);
    }
    __syncthreads();

    for (int it = 0; it < NIT; it++) {
        int cur = it & 1;
        bool has_next = (it + 1 < NIT);
        Prefetch pr;
        if (has_next) pr = load_chunk(x, it + 1, tid, poff, n_img);

        uint32_t abase = smem_u32(sA[cur]);
        uint32_t bbase = smem_u32(sB[cur]);

        #pragma unroll
        for (int ks = 0; ks < 3; ks++) {
            int kb = ks * 16;
            uint32_t afr[4][4], bfr[2][2];
            #pragma unroll
            for (int mi = 0; mi < 4; mi++) {
                int row = wm * 64 + mi * 16 + a_row_l;
                int col = kb + a_col_l;
                ldsm_x4(afr[mi], abase + (uint32_t)(row * SA + col) * 2u);
            }
            #pragma unroll
            for (int ni = 0; ni < 2; ni++) {
                int krow = kb + b_row_l;
                int n0 = wn * 16 + ni * 8;
                ldsm_x2_t(bfr[ni], bbase + (uint32_t)(krow * SB + n0) * 2u);
            }
            #pragma unroll
            for (int mi = 0; mi < 4; mi++)
                #pragma unroll
                for (int ni = 0; ni < 2; ni++)
                    mma16816(acc[mi][ni], afr[mi], bfr[ni]);
        }

        if (has_next) store_chunk(pr, tid, sA[cur ^ 1], sB[cur ^ 1]);
        __syncthreads();
    }

    // Epilogue: acc frag (mi,ni): d0,d1 -> (row, col..col+1); d2,d3 -> row+8
    float* ob = out + (size_t)n_img * (OUT_CH * 1024) + poff;
    #pragma unroll
    for (int mi = 0; mi < 4; mi++) {
        #pragma unroll
        for (int ni = 0; ni < 2; ni++) {
            int row = wm * 64 + mi * 16 + (lane >> 2);
            int col = wn * 16 + ni * 8 + (lane & 3) * 2;
            float2 v0 = make_float2(acc[mi][ni][0], acc[mi][ni][1]);
            float2 v1 = make_float2(acc[mi][ni][2], acc[mi][ni][3]);
            *reinterpret_cast<float2*>(ob + (size_t)row * 1024 + col) = v0;
            *reinterpret_cast<float2*>(ob + (size_t)(row + 8) * 1024 + col) = v1;
        }
    }
}

// ============================================================================
// Host launcher. Inputs: x, knots(unused: fixed uniform grid), coeff, bw, sw.
// ============================================================================
extern "C" void kernel_launch(void* const* d_in, const int* in_sizes, int n_in,
                              void* d_out, int out_size) {
    const float* x     = (const float*)d_in[0];
    const float* coeff = (const float*)d_in[2];
    const float* bw    = (const float*)d_in[3];
    const float* sw    = (const float*)d_in[4];
    float* out = (float*)d_out;
    (void)in_sizes; (void)n_in; (void)out_size;

    build_w_kernel<<<(OUT_CH * K_TOTAL + 255) / 256, 256>>>(coeff, bw, sw);
    fused_gemm_kernel<<<128, 256>>>(x, out);
}